// round 4
// baseline (speedup 1.0000x reference)
#include <cuda_runtime.h>
#include <cuda_fp16.h>
#include <math.h>
#include <cstdint>

#define B_    8
#define L_    4096
#define D_    384
#define DI_   768
#define S_    16
#define DTR_  24
#define KC_   4
#define NC_   40
#define T_    (B_*L_)          // 32768 tokens
#define XDN_  (DTR_ + 2*S_)    // 56
#define NI_   (2*DI_)          // 1536
#define EPS_  1e-5f
#define NCHK_ 4
#define CL_   (L_/NCHK_)       // 1024
#define NST_  (B_*DI_*16)      // per-chunk state floats

// ======================= mma helpers =======================
__device__ __forceinline__ uint32_t f2tf32(float x) {
    uint32_t r; asm("cvt.rna.tf32.f32 %0, %1;" : "=r"(r) : "f"(x)); return r;
}
__device__ __forceinline__ void mma_tf32(float* c, const uint32_t* a, const uint32_t* b) {
    asm volatile(
        "mma.sync.aligned.m16n8k8.row.col.f32.tf32.tf32.f32 "
        "{%0,%1,%2,%3}, {%4,%5,%6,%7}, {%8,%9}, {%0,%1,%2,%3};\n"
        : "+f"(c[0]), "+f"(c[1]), "+f"(c[2]), "+f"(c[3])
        : "r"(a[0]), "r"(a[1]), "r"(a[2]), "r"(a[3]), "r"(b[0]), "r"(b[1]));
}
__device__ __forceinline__ void mma_f16(float* c, const uint32_t* a, const uint32_t* b) {
    asm volatile(
        "mma.sync.aligned.m16n8k16.row.col.f32.f16.f16.f32 "
        "{%0,%1,%2,%3}, {%4,%5,%6,%7}, {%8,%9}, {%0,%1,%2,%3};\n"
        : "+f"(c[0]), "+f"(c[1]), "+f"(c[2]), "+f"(c[3])
        : "r"(a[0]), "r"(a[1]), "r"(a[2]), "r"(a[3]), "r"(b[0]), "r"(b[1]));
}

// ======================= scratch =======================
__device__ __align__(128) __half g_xnh [T_ * D_];        // rmsnorm output (half)
__device__ __align__(128) __half g_wth [NI_ * D_];       // W_in^T (half) [1536][384]
__device__ __align__(128) float  g_xz  [T_ * NI_];       // xn @ W_in (xp | z), fp32
__device__ __align__(128) float  g_xc  [T_ * DI_];       // conv+silu output
__device__ __align__(128) float  g_wt2 [64 * DI_];       // W_xproj^T zero-padded [64][768]
__device__ __align__(128) float  g_xdbl[T_ * XDN_];      // xc @ W_xproj
__device__ __align__(128) float  g_dtx [T_ * DI_ * 2];   // (dt, xc) float2
__device__ __align__(128) float  g_bc2 [T_ * 4 * 8];     // [t][grp][B0..3,C0..3]
__device__ float g_se [3 * NST_];                        // chunk-local end states
__device__ float g_sp [3 * NST_];                        // chunk dA products
__device__ float g_hs [3 * NST_];                        // chunk start states (c=1..3)
__device__ float g_yp2[NCHK_ * B_ * DI_];
__device__ float g_xpart[64 * B_ * D_];
__device__ float g_ym   [B_ * DI_];
__device__ float g_xmean[B_ * D_];
__device__ float g_pooled[B_ * D_];

// ======================= RMSNorm -> half =======================
__global__ void k_rmsnorm(const float* __restrict__ x, const float* __restrict__ ln_w) {
    int t = blockIdx.x;
    const float* xr = x + (size_t)t * D_;
    float ss = 0.f;
    for (int d = threadIdx.x; d < D_; d += 128) { float v = xr[d]; ss += v * v; }
    #pragma unroll
    for (int o = 16; o; o >>= 1) ss += __shfl_xor_sync(0xffffffffu, ss, o);
    __shared__ float sw[4];
    if ((threadIdx.x & 31) == 0) sw[threadIdx.x >> 5] = ss;
    __syncthreads();
    float tot = sw[0] + sw[1] + sw[2] + sw[3];
    float rs = rsqrtf(tot * (1.f / D_) + EPS_);
    for (int d = threadIdx.x; d < D_; d += 128)
        g_xnh[(size_t)t * D_ + d] = __float2half_rn(xr[d] * rs * ln_w[d]);
}

// ======================= W_in transpose -> half =======================
__global__ void k_wt(const float* __restrict__ W_in) {
    __shared__ float tile[32][33];
    int k0 = blockIdx.x * 32, n0 = blockIdx.y * 32;
    int tx = threadIdx.x & 31, ty = threadIdx.x >> 5;
    for (int i = 0; i < 32; i += 8)
        tile[ty + i][tx] = W_in[(size_t)(k0 + ty + i) * NI_ + n0 + tx];
    __syncthreads();
    for (int i = 0; i < 32; i += 8)
        g_wth[(size_t)(n0 + ty + i) * D_ + k0 + tx] = __float2half_rn(tile[tx][ty + i]);
}

// ======================= W_xproj transpose, zero-padded to 64 rows =======================
__global__ void k_wt2(const float* __restrict__ W) {
    __shared__ float tile[32][33];
    int k0 = blockIdx.x * 32, n0 = blockIdx.y * 32;
    int tx = threadIdx.x & 31, ty = threadIdx.x >> 5;
    for (int i = 0; i < 32; i += 8)
        tile[ty + i][tx] = (n0 + tx < XDN_) ? W[(size_t)(k0 + ty + i) * XDN_ + n0 + tx] : 0.f;
    __syncthreads();
    for (int i = 0; i < 32; i += 8)
        g_wt2[(size_t)(n0 + ty + i) * DI_ + k0 + tx] = tile[tx][ty + i];
}

// ======================= GEMM1: fp16 mma, xz[T,1536] = xnh @ W_in =======================
// 128x128x32 tile, 256 thr, 8 warps (2x4), warp tile 64x32, 2 k16 steps per chunk.
#define G1P_ 40   // halfs per smem row

__global__ void __launch_bounds__(256, 2) k_gemm1(const __half* __restrict__ A,
                                                  const __half* __restrict__ Bt,
                                                  float* __restrict__ C) {
    __shared__ __half sA[128 * G1P_];
    __shared__ __half sB[128 * G1P_];
    int tid = threadIdx.x;
    int lane = tid & 31, wid = tid >> 5;
    int wm = wid >> 2, wn = wid & 3;
    int gid = lane >> 2, tig = lane & 3;
    int m0 = blockIdx.y * 128, n0 = blockIdx.x * 128;

    float acc[4][4][4];
    #pragma unroll
    for (int i = 0; i < 4; i++)
        #pragma unroll
        for (int j = 0; j < 4; j++)
            #pragma unroll
            for (int q = 0; q < 4; q++) acc[i][j][q] = 0.f;

    for (int k0 = 0; k0 < D_; k0 += 32) {
        #pragma unroll
        for (int i = 0; i < 2; i++) {
            int f = tid + i * 256;
            int row = f >> 2, c8 = f & 3;
            *(float4*)&sA[row * G1P_ + c8 * 8] =
                *(const float4*)&A[(size_t)(m0 + row) * D_ + k0 + c8 * 8];
        }
        #pragma unroll
        for (int i = 0; i < 2; i++) {
            int f = tid + i * 256;
            int row = f >> 2, c8 = f & 3;
            *(float4*)&sB[row * G1P_ + c8 * 8] =
                *(const float4*)&Bt[(size_t)(n0 + row) * D_ + k0 + c8 * 8];
        }
        __syncthreads();
        #pragma unroll
        for (int kk = 0; kk < 32; kk += 16) {
            uint32_t af[4][4], bf[4][2];
            #pragma unroll
            for (int mt = 0; mt < 4; mt++) {
                int r = wm * 64 + mt * 16 + gid;
                af[mt][0] = *(uint32_t*)&sA[r * G1P_ + kk + 2 * tig];
                af[mt][1] = *(uint32_t*)&sA[(r + 8) * G1P_ + kk + 2 * tig];
                af[mt][2] = *(uint32_t*)&sA[r * G1P_ + kk + 2 * tig + 8];
                af[mt][3] = *(uint32_t*)&sA[(r + 8) * G1P_ + kk + 2 * tig + 8];
            }
            #pragma unroll
            for (int nt = 0; nt < 4; nt++) {
                int r = wn * 32 + nt * 8 + gid;
                bf[nt][0] = *(uint32_t*)&sB[r * G1P_ + kk + 2 * tig];
                bf[nt][1] = *(uint32_t*)&sB[r * G1P_ + kk + 2 * tig + 8];
            }
            #pragma unroll
            for (int mt = 0; mt < 4; mt++)
                #pragma unroll
                for (int nt = 0; nt < 4; nt++)
                    mma_f16(acc[mt][nt], af[mt], bf[nt]);
        }
        __syncthreads();
    }
    #pragma unroll
    for (int mt = 0; mt < 4; mt++) {
        int row = m0 + wm * 64 + mt * 16 + gid;
        #pragma unroll
        for (int nt = 0; nt < 4; nt++) {
            int col = n0 + wn * 32 + nt * 8 + 2 * tig;
            *(float2*)&C[(size_t)row * NI_ + col]       = make_float2(acc[mt][nt][0], acc[mt][nt][1]);
            *(float2*)&C[(size_t)(row + 8) * NI_ + col] = make_float2(acc[mt][nt][2], acc[mt][nt][3]);
        }
    }
}

// ======================= GEMM2: tf32 mma, x_dbl[T,56] = xc[T,768] @ W_xproj =======================
// 128x64x32 tile, 256 thr, 8 warps (4x2), warp tile 32x32.
#define G2P_ 36

__global__ void __launch_bounds__(256, 2) k_gemm2(const float* __restrict__ A,
                                                  const float* __restrict__ Bt,
                                                  float* __restrict__ C) {
    __shared__ uint32_t sA[128 * G2P_];
    __shared__ uint32_t sB[64 * G2P_];
    int tid = threadIdx.x;
    int lane = tid & 31, wid = tid >> 5;
    int wm = wid >> 1, wn = wid & 1;
    int gid = lane >> 2, tig = lane & 3;
    int m0 = blockIdx.x * 128;

    float acc[2][4][4];
    #pragma unroll
    for (int i = 0; i < 2; i++)
        #pragma unroll
        for (int j = 0; j < 4; j++)
            #pragma unroll
            for (int q = 0; q < 4; q++) acc[i][j][q] = 0.f;

    for (int k0 = 0; k0 < DI_; k0 += 32) {
        #pragma unroll
        for (int i = 0; i < 4; i++) {
            int f = tid + i * 256;
            int row = f >> 3, c4 = f & 7;
            float4 v = *(const float4*)&A[(size_t)(m0 + row) * DI_ + k0 + c4 * 4];
            uint32_t* d = &sA[row * G2P_ + c4 * 4];
            d[0] = f2tf32(v.x); d[1] = f2tf32(v.y); d[2] = f2tf32(v.z); d[3] = f2tf32(v.w);
        }
        #pragma unroll
        for (int i = 0; i < 2; i++) {
            int f = tid + i * 256;
            int row = f >> 3, c4 = f & 7;
            float4 v = *(const float4*)&Bt[(size_t)row * DI_ + k0 + c4 * 4];
            uint32_t* d = &sB[row * G2P_ + c4 * 4];
            d[0] = f2tf32(v.x); d[1] = f2tf32(v.y); d[2] = f2tf32(v.z); d[3] = f2tf32(v.w);
        }
        __syncthreads();
        #pragma unroll
        for (int kk = 0; kk < 32; kk += 8) {
            uint32_t af[2][4], bf[4][2];
            #pragma unroll
            for (int mt = 0; mt < 2; mt++) {
                int r = wm * 32 + mt * 16 + gid;
                af[mt][0] = sA[r * G2P_ + kk + tig];
                af[mt][1] = sA[(r + 8) * G2P_ + kk + tig];
                af[mt][2] = sA[r * G2P_ + kk + tig + 4];
                af[mt][3] = sA[(r + 8) * G2P_ + kk + tig + 4];
            }
            #pragma unroll
            for (int nt = 0; nt < 4; nt++) {
                int r = wn * 32 + nt * 8 + gid;
                bf[nt][0] = sB[r * G2P_ + kk + tig];
                bf[nt][1] = sB[r * G2P_ + kk + tig + 4];
            }
            #pragma unroll
            for (int mt = 0; mt < 2; mt++)
                #pragma unroll
                for (int nt = 0; nt < 4; nt++)
                    mma_tf32(acc[mt][nt], af[mt], bf[nt]);
        }
        __syncthreads();
    }
    #pragma unroll
    for (int mt = 0; mt < 2; mt++) {
        int row = m0 + wm * 32 + mt * 16 + gid;
        #pragma unroll
        for (int nt = 0; nt < 4; nt++) {
            int col = wn * 32 + nt * 8 + 2 * tig;
            if (col < XDN_) {
                *(float2*)&C[(size_t)row * XDN_ + col]       = make_float2(acc[mt][nt][0], acc[mt][nt][1]);
                *(float2*)&C[(size_t)(row + 8) * XDN_ + col] = make_float2(acc[mt][nt][2], acc[mt][nt][3]);
            }
        }
    }
}

// ======================= causal depthwise conv (K=4) + SiLU =======================
__global__ void k_conv(const float* __restrict__ conv_w, const float* __restrict__ conv_b) {
    int idx = blockIdx.x * 256 + threadIdx.x;
    if (idx >= T_ * DI_) return;
    int di = idx % DI_;
    int t  = idx / DI_;
    int l  = t & (L_ - 1);
    float acc = conv_b[di];
    #pragma unroll
    for (int k = 0; k < KC_; k++) {
        int ll = l - (KC_ - 1) + k;
        if (ll >= 0)
            acc = fmaf(conv_w[di * KC_ + k], g_xz[(size_t)(t - (KC_ - 1) + k) * NI_ + di], acc);
    }
    float sg = 1.f / (1.f + __expf(-acc));
    g_xc[(size_t)t * DI_ + di] = acc * sg;
}

// ======================= dt = softplus(dt_r @ W_dt + bias); writes (dt,xc) float2 =======================
__global__ void k_dt(const float* __restrict__ W_dt, const float* __restrict__ dt_bias) {
    __shared__ float s_dtr[8][DTR_];
    int t0 = blockIdx.x * 8;
    int tid = threadIdx.x;
    if (tid < 8 * DTR_) {
        int tt = tid / DTR_, rr = tid % DTR_;
        s_dtr[tt][rr] = g_xdbl[(size_t)(t0 + tt) * XDN_ + rr];
    }
    __syncthreads();
    int di = tid;
    float bias = dt_bias[di];
    float acc[8];
    #pragma unroll
    for (int tt = 0; tt < 8; tt++) acc[tt] = bias;
    for (int rr = 0; rr < DTR_; rr++) {
        float w = W_dt[rr * DI_ + di];
        #pragma unroll
        for (int tt = 0; tt < 8; tt++) acc[tt] = fmaf(s_dtr[tt][rr], w, acc[tt]);
    }
    #pragma unroll
    for (int tt = 0; tt < 8; tt++) {
        float v = acc[tt];
        float sp = (v > 20.f) ? v : log1pf(__expf(v));
        size_t i = (size_t)(t0 + tt) * DI_ + di;
        ((float2*)g_dtx)[i] = make_float2(sp, g_xc[i]);
    }
}

// ======================= pack B/C into [t][grp][B0..3,C0..3] =======================
__global__ void k_bcpack() {
    int idx = blockIdx.x * 256 + threadIdx.x;   // T_*4
    if (idx >= T_ * 4) return;
    int t = idx >> 2, grp = idx & 3;
    const float* base = &g_xdbl[(size_t)t * XDN_ + DTR_];
    float4 Bv = *(const float4*)&base[grp * 4];
    float4 Cv = *(const float4*)&base[S_ + grp * 4];
    float* o = &g_bc2[(size_t)idx * 8];
    *(float4*)o = Bv;
    *(float4*)(o + 4) = Cv;
}

// ======================= scan pass A: chunk-local end state + dA product (chunks 0..2) =======================
__global__ void __launch_bounds__(128) k_scanA(const float* __restrict__ A_log) {
    int di_l = threadIdx.x >> 2, grp = threadIdx.x & 3;
    int di = blockIdx.x * 32 + di_l;
    int b = blockIdx.y, c = blockIdx.z;
    float A[4], h[4] = {0.f, 0.f, 0.f, 0.f}, P[4] = {1.f, 1.f, 1.f, 1.f};
    #pragma unroll
    for (int j = 0; j < 4; j++) A[j] = -__expf(A_log[di * S_ + grp * 4 + j]);
    size_t t0 = (size_t)b * L_ + (size_t)c * CL_;
    const float2* dtx = (const float2*)g_dtx;
    for (int l = 0; l < CL_; l++) {
        size_t t = t0 + l;
        float2 dx = dtx[t * DI_ + di];
        float4 B4 = *(const float4*)&g_bc2[(t * 4 + grp) * 8];
        float dxx = dx.x * dx.y;
        float dA0 = __expf(dx.x * A[0]), dA1 = __expf(dx.x * A[1]);
        float dA2 = __expf(dx.x * A[2]), dA3 = __expf(dx.x * A[3]);
        h[0] = fmaf(dA0, h[0], dxx * B4.x); P[0] *= dA0;
        h[1] = fmaf(dA1, h[1], dxx * B4.y); P[1] *= dA1;
        h[2] = fmaf(dA2, h[2], dxx * B4.z); P[2] *= dA2;
        h[3] = fmaf(dA3, h[3], dxx * B4.w); P[3] *= dA3;
    }
    size_t f = ((size_t)(b * DI_ + di) * 16 + grp * 4);
    *(float4*)&g_se[(size_t)c * NST_ + f] = make_float4(h[0], h[1], h[2], h[3]);
    *(float4*)&g_sp[(size_t)c * NST_ + f] = make_float4(P[0], P[1], P[2], P[3]);
}

// ======================= scan fixup: chunk start states =======================
__global__ void k_scanF() {
    int i = blockIdx.x * 256 + threadIdx.x;   // NST_ = 98304
    float e0 = g_se[i];
    float hs1 = e0;
    float E1  = fmaf(g_sp[NST_ + i], hs1, g_se[NST_ + i]);
    float hs3 = fmaf(g_sp[2 * NST_ + i], E1, g_se[2 * NST_ + i]);
    g_hs[i] = hs1;
    g_hs[NST_ + i] = E1;
    g_hs[2 * NST_ + i] = hs3;
}

// ======================= scan pass B: full scan + gate + pooled partial =======================
__global__ void __launch_bounds__(128) k_scanB(const float* __restrict__ A_log,
                                               const float* __restrict__ Dskip) {
    int di_l = threadIdx.x >> 2, grp = threadIdx.x & 3;
    int di = blockIdx.x * 32 + di_l;
    int b = blockIdx.y, c = blockIdx.z;
    float A[4], h[4];
    #pragma unroll
    for (int j = 0; j < 4; j++) A[j] = -__expf(A_log[di * S_ + grp * 4 + j]);
    size_t f = ((size_t)(b * DI_ + di) * 16 + grp * 4);
    if (c == 0) { h[0] = h[1] = h[2] = h[3] = 0.f; }
    else {
        float4 v = *(const float4*)&g_hs[(size_t)(c - 1) * NST_ + f];
        h[0] = v.x; h[1] = v.y; h[2] = v.z; h[3] = v.w;
    }
    float ds = Dskip[di];
    float acc = 0.f;
    size_t t0 = (size_t)b * L_ + (size_t)c * CL_;
    const float2* dtx = (const float2*)g_dtx;
    for (int l = 0; l < CL_; l++) {
        size_t t = t0 + l;
        float2 dx = dtx[t * DI_ + di];
        const float* bp = &g_bc2[(t * 4 + grp) * 8];
        float4 B4 = *(const float4*)bp;
        float4 C4 = *(const float4*)(bp + 4);
        float dxx = dx.x * dx.y;
        float dA0 = __expf(dx.x * A[0]), dA1 = __expf(dx.x * A[1]);
        float dA2 = __expf(dx.x * A[2]), dA3 = __expf(dx.x * A[3]);
        h[0] = fmaf(dA0, h[0], dxx * B4.x);
        h[1] = fmaf(dA1, h[1], dxx * B4.y);
        h[2] = fmaf(dA2, h[2], dxx * B4.z);
        h[3] = fmaf(dA3, h[3], dxx * B4.w);
        float yp = h[0] * C4.x + h[1] * C4.y + h[2] * C4.z + h[3] * C4.w;
        yp += __shfl_xor_sync(0xffffffffu, yp, 1);
        yp += __shfl_xor_sync(0xffffffffu, yp, 2);
        if (grp == 0) {
            float z = g_xz[t * NI_ + DI_ + di];
            float sz = z / (1.f + __expf(-z));
            acc += (yp + dx.y * ds) * sz;
        }
    }
    if (grp == 0) g_yp2[(size_t)(c * B_ + b) * DI_ + di] = acc;
}

// ======================= means / pooled / head =======================
__global__ void k_ymean() {
    int i = blockIdx.x * 256 + threadIdx.x;    // B_*DI_
    float acc = 0.f;
    #pragma unroll
    for (int c = 0; c < NCHK_; c++) acc += g_yp2[(size_t)c * B_ * DI_ + i];
    g_ym[i] = acc * (1.f / L_);
}
__global__ void k_xpart(const float* __restrict__ x) {
    int d = threadIdx.x;
    int chunk = blockIdx.x;
    int b = blockIdx.y;
    float acc = 0.f;
    int t0 = b * L_ + chunk * 64;
    for (int i = 0; i < 64; i++) acc += x[(size_t)(t0 + i) * D_ + d];
    g_xpart[(size_t)(chunk * B_ + b) * D_ + d] = acc;
}
__global__ void k_xmean() {
    int i = blockIdx.x * 256 + threadIdx.x;
    float acc = 0.f;
    for (int c = 0; c < 64; c++) acc += g_xpart[(size_t)c * B_ * D_ + i];
    g_xmean[i] = acc * (1.f / L_);
}
__global__ void k_pooled(const float* __restrict__ W_out) {
    int d = threadIdx.x;
    int b = blockIdx.x;
    float acc = g_xmean[b * D_ + d];
    for (int di = 0; di < DI_; di++)
        acc = fmaf(g_ym[b * DI_ + di], W_out[(size_t)di * D_ + d], acc);
    g_pooled[b * D_ + d] = acc;
}
__global__ void k_head(const float* __restrict__ W_fc, const float* __restrict__ b_fc,
                       const float* __restrict__ gamma, const float* __restrict__ beta,
                       const float* __restrict__ W_cls, const float* __restrict__ b_cls,
                       float* __restrict__ out) {
    __shared__ float sp[B_][D_];
    __shared__ float sh[B_][256];
    int tid = threadIdx.x;
    for (int i = tid; i < B_ * D_; i += 256) sp[i / D_][i % D_] = g_pooled[i];
    __syncthreads();
    int j = tid;
    float hv[B_];
    #pragma unroll
    for (int b = 0; b < B_; b++) hv[b] = b_fc[j];
    for (int k = 0; k < D_; k++) {
        float w = W_fc[(size_t)k * 256 + j];
        #pragma unroll
        for (int b = 0; b < B_; b++) hv[b] = fmaf(sp[b][k], w, hv[b]);
    }
    float mu = 0.f;
    #pragma unroll
    for (int b = 0; b < B_; b++) mu += hv[b];
    mu *= (1.f / B_);
    float var = 0.f;
    #pragma unroll
    for (int b = 0; b < B_; b++) { float dd = hv[b] - mu; var += dd * dd; }
    var *= (1.f / B_);
    float rs = rsqrtf(var + EPS_);
    float g = gamma[j], bt = beta[j];
    #pragma unroll
    for (int b = 0; b < B_; b++) {
        float v = (hv[b] - mu) * rs * g + bt;
        sh[b][j] = v > 0.f ? v : 0.f;
    }
    __syncthreads();
    for (int o = tid; o < B_ * NC_; o += 256) {
        int b = o / NC_, c = o % NC_;
        float acc = b_cls[c];
        for (int k = 0; k < 256; k++) acc = fmaf(sh[b][k], W_cls[k * NC_ + c], acc);
        out[o] = acc;
    }
}

// ======================= launch =======================
extern "C" void kernel_launch(void* const* d_in, const int* in_sizes, int n_in,
                              void* d_out, int out_size) {
    const float* x       = (const float*)d_in[0];
    const float* ln_w    = (const float*)d_in[1];
    const float* W_in    = (const float*)d_in[2];
    const float* conv_w  = (const float*)d_in[3];
    const float* conv_b  = (const float*)d_in[4];
    const float* W_xproj = (const float*)d_in[5];
    const float* W_dt    = (const float*)d_in[6];
    const float* dt_bias = (const float*)d_in[7];
    const float* A_log   = (const float*)d_in[8];
    const float* Dskip   = (const float*)d_in[9];
    const float* W_out   = (const float*)d_in[10];
    const float* W_fc    = (const float*)d_in[11];
    const float* b_fc    = (const float*)d_in[12];
    const float* bn_g    = (const float*)d_in[13];
    const float* bn_b    = (const float*)d_in[14];
    const float* W_cls   = (const float*)d_in[15];
    const float* b_cls   = (const float*)d_in[16];
    float* out = (float*)d_out;

    __half *p_xnh, *p_wth;
    float *p_xz, *p_xc, *p_wt2, *p_xdbl;
    cudaGetSymbolAddress((void**)&p_xnh,  g_xnh);
    cudaGetSymbolAddress((void**)&p_wth,  g_wth);
    cudaGetSymbolAddress((void**)&p_xz,   g_xz);
    cudaGetSymbolAddress((void**)&p_xc,   g_xc);
    cudaGetSymbolAddress((void**)&p_wt2,  g_wt2);
    cudaGetSymbolAddress((void**)&p_xdbl, g_xdbl);

    // 1. RMSNorm (half out) + weight transposes
    k_rmsnorm<<<T_, 128>>>(x, ln_w);
    k_wt<<<dim3(D_ / 32, NI_ / 32), 256>>>(W_in);
    k_wt2<<<dim3(DI_ / 32, 2), 256>>>(W_xproj);
    // 2. xz = xn @ W_in  — fp16 mma
    k_gemm1<<<dim3(NI_ / 128, T_ / 128), 256>>>(p_xnh, p_wth, p_xz);
    // 3. conv + silu
    k_conv<<<(T_ * DI_ + 255) / 256, 256>>>(conv_w, conv_b);
    // 4. x_dbl = xc @ W_xproj — tf32 mma
    k_gemm2<<<T_ / 128, 256>>>(p_xc, p_wt2, p_xdbl);
    // 5. dt (+pack) and BC pack
    k_dt<<<T_ / 8, DI_>>>(W_dt, dt_bias);
    k_bcpack<<<(T_ * 4 + 255) / 256, 256>>>();
    // 6. chunked selective scan (A: states, F: fixup, B: full + gate + pool)
    k_scanA<<<dim3(DI_ / 32, B_, NCHK_ - 1), 128>>>(A_log);
    k_scanF<<<NST_ / 256, 256>>>();
    k_scanB<<<dim3(DI_ / 32, B_, NCHK_), 128>>>(A_log, Dskip);
    // 7. means + pooled + head
    k_ymean<<<(B_ * DI_) / 256, 256>>>();
    k_xpart<<<dim3(64, B_), D_>>>(x);
    k_xmean<<<(B_ * D_) / 256, 256>>>();
    k_pooled<<<B_, D_>>>(W_out);
    k_head<<<1, 256>>>(W_fc, b_fc, bn_g, bn_b, W_cls, b_cls, out);
}

// round 5
// speedup vs baseline: 1.3476x; 1.3476x over previous
#include <cuda_runtime.h>
#include <cuda_fp16.h>
#include <math.h>
#include <cstdint>

#define B_    8
#define L_    4096
#define D_    384
#define DI_   768
#define S_    16
#define DTR_  24
#define KC_   4
#define NC_   40
#define T_    (B_*L_)          // 32768 tokens
#define XDN_  (DTR_ + 2*S_)    // 56
#define NI_   (2*DI_)          // 1536
#define EPS_  1e-5f

// ======================= mma helpers =======================
__device__ __forceinline__ uint32_t f2tf32(float x) {
    uint32_t r; asm("cvt.rna.tf32.f32 %0, %1;" : "=r"(r) : "f"(x)); return r;
}
__device__ __forceinline__ void mma_tf32(float* c, const uint32_t* a, const uint32_t* b) {
    asm volatile(
        "mma.sync.aligned.m16n8k8.row.col.f32.tf32.tf32.f32 "
        "{%0,%1,%2,%3}, {%4,%5,%6,%7}, {%8,%9}, {%0,%1,%2,%3};\n"
        : "+f"(c[0]), "+f"(c[1]), "+f"(c[2]), "+f"(c[3])
        : "r"(a[0]), "r"(a[1]), "r"(a[2]), "r"(a[3]), "r"(b[0]), "r"(b[1]));
}
__device__ __forceinline__ void mma_f16(float* c, const uint32_t* a, const uint32_t* b) {
    asm volatile(
        "mma.sync.aligned.m16n8k16.row.col.f32.f16.f16.f32 "
        "{%0,%1,%2,%3}, {%4,%5,%6,%7}, {%8,%9}, {%0,%1,%2,%3};\n"
        : "+f"(c[0]), "+f"(c[1]), "+f"(c[2]), "+f"(c[3])
        : "r"(a[0]), "r"(a[1]), "r"(a[2]), "r"(a[3]), "r"(b[0]), "r"(b[1]));
}

// ======================= scratch =======================
__device__ __align__(128) __half g_xnh [T_ * D_];        // rmsnorm output (half)
__device__ __align__(128) __half g_wth [NI_ * D_];       // W_in^T (half) [1536][384]
__device__ __align__(128) float  g_xz  [T_ * NI_];       // xn @ W_in (xp | z)
__device__ __align__(128) float  g_xc  [T_ * DI_];       // conv+silu output
__device__ __align__(128) float  g_wt2 [64 * DI_];       // W_xproj^T zero-padded [64][768]
__device__ __align__(128) float  g_xdbl[T_ * XDN_];      // xc @ W_xproj
__device__ __align__(128) float  g_dtx [T_ * DI_ * 2];   // (dt, xc) interleaved
__device__ __align__(128) float  g_bc  [T_ * S_ * 2];    // (B, C) interleaved
__device__ __align__(128) float  g_y   [T_ * DI_];       // scan output
__device__ float g_ypart[64 * B_ * DI_];
__device__ float g_xpart[64 * B_ * D_];
__device__ float g_ym   [B_ * DI_];
__device__ float g_xmean[B_ * D_];
__device__ float g_pooled[B_ * D_];

// ======================= RMSNorm -> half =======================
__global__ void k_rmsnorm(const float* __restrict__ x, const float* __restrict__ ln_w) {
    int t = blockIdx.x;
    const float* xr = x + (size_t)t * D_;
    float ss = 0.f;
    for (int d = threadIdx.x; d < D_; d += 128) { float v = xr[d]; ss += v * v; }
    #pragma unroll
    for (int o = 16; o; o >>= 1) ss += __shfl_xor_sync(0xffffffffu, ss, o);
    __shared__ float sw[4];
    if ((threadIdx.x & 31) == 0) sw[threadIdx.x >> 5] = ss;
    __syncthreads();
    float tot = sw[0] + sw[1] + sw[2] + sw[3];
    float rs = rsqrtf(tot * (1.f / D_) + EPS_);
    for (int d = threadIdx.x; d < D_; d += 128)
        g_xnh[(size_t)t * D_ + d] = __float2half_rn(xr[d] * rs * ln_w[d]);
}

// ======================= W_in transpose -> half =======================
__global__ void k_wt(const float* __restrict__ W_in) {
    __shared__ float tile[32][33];
    int k0 = blockIdx.x * 32, n0 = blockIdx.y * 32;
    int tx = threadIdx.x & 31, ty = threadIdx.x >> 5;
    for (int i = 0; i < 32; i += 8)
        tile[ty + i][tx] = W_in[(size_t)(k0 + ty + i) * NI_ + n0 + tx];
    __syncthreads();
    for (int i = 0; i < 32; i += 8)
        g_wth[(size_t)(n0 + ty + i) * D_ + k0 + tx] = __float2half_rn(tile[tx][ty + i]);
}

// ======================= W_xproj transpose, zero-padded to 64 rows =======================
__global__ void k_wt2(const float* __restrict__ W) {
    __shared__ float tile[32][33];
    int k0 = blockIdx.x * 32, n0 = blockIdx.y * 32;
    int tx = threadIdx.x & 31, ty = threadIdx.x >> 5;
    for (int i = 0; i < 32; i += 8)
        tile[ty + i][tx] = (n0 + tx < XDN_) ? W[(size_t)(k0 + ty + i) * XDN_ + n0 + tx] : 0.f;
    __syncthreads();
    for (int i = 0; i < 32; i += 8)
        g_wt2[(size_t)(n0 + ty + i) * DI_ + k0 + tx] = tile[tx][ty + i];
}

// ======================= GEMM1: fp16 mma, xz[T,1536] = xnh @ W_in (measured 193us) ============
#define G1P_ 40   // halfs per smem row

__global__ void __launch_bounds__(256, 2) k_gemm1(const __half* __restrict__ A,
                                                  const __half* __restrict__ Bt,
                                                  float* __restrict__ C) {
    __shared__ __half sA[128 * G1P_];
    __shared__ __half sB[128 * G1P_];
    int tid = threadIdx.x;
    int lane = tid & 31, wid = tid >> 5;
    int wm = wid >> 2, wn = wid & 3;
    int gid = lane >> 2, tig = lane & 3;
    int m0 = blockIdx.y * 128, n0 = blockIdx.x * 128;

    float acc[4][4][4];
    #pragma unroll
    for (int i = 0; i < 4; i++)
        #pragma unroll
        for (int j = 0; j < 4; j++)
            #pragma unroll
            for (int q = 0; q < 4; q++) acc[i][j][q] = 0.f;

    for (int k0 = 0; k0 < D_; k0 += 32) {
        #pragma unroll
        for (int i = 0; i < 2; i++) {
            int f = tid + i * 256;
            int row = f >> 2, c8 = f & 3;
            *(float4*)&sA[row * G1P_ + c8 * 8] =
                *(const float4*)&A[(size_t)(m0 + row) * D_ + k0 + c8 * 8];
        }
        #pragma unroll
        for (int i = 0; i < 2; i++) {
            int f = tid + i * 256;
            int row = f >> 2, c8 = f & 3;
            *(float4*)&sB[row * G1P_ + c8 * 8] =
                *(const float4*)&Bt[(size_t)(n0 + row) * D_ + k0 + c8 * 8];
        }
        __syncthreads();
        #pragma unroll
        for (int kk = 0; kk < 32; kk += 16) {
            uint32_t af[4][4], bf[4][2];
            #pragma unroll
            for (int mt = 0; mt < 4; mt++) {
                int r = wm * 64 + mt * 16 + gid;
                af[mt][0] = *(uint32_t*)&sA[r * G1P_ + kk + 2 * tig];
                af[mt][1] = *(uint32_t*)&sA[(r + 8) * G1P_ + kk + 2 * tig];
                af[mt][2] = *(uint32_t*)&sA[r * G1P_ + kk + 2 * tig + 8];
                af[mt][3] = *(uint32_t*)&sA[(r + 8) * G1P_ + kk + 2 * tig + 8];
            }
            #pragma unroll
            for (int nt = 0; nt < 4; nt++) {
                int r = wn * 32 + nt * 8 + gid;
                bf[nt][0] = *(uint32_t*)&sB[r * G1P_ + kk + 2 * tig];
                bf[nt][1] = *(uint32_t*)&sB[r * G1P_ + kk + 2 * tig + 8];
            }
            #pragma unroll
            for (int mt = 0; mt < 4; mt++)
                #pragma unroll
                for (int nt = 0; nt < 4; nt++)
                    mma_f16(acc[mt][nt], af[mt], bf[nt]);
        }
        __syncthreads();
    }
    #pragma unroll
    for (int mt = 0; mt < 4; mt++) {
        int row = m0 + wm * 64 + mt * 16 + gid;
        #pragma unroll
        for (int nt = 0; nt < 4; nt++) {
            int col = n0 + wn * 32 + nt * 8 + 2 * tig;
            *(float2*)&C[(size_t)row * NI_ + col]       = make_float2(acc[mt][nt][0], acc[mt][nt][1]);
            *(float2*)&C[(size_t)(row + 8) * NI_ + col] = make_float2(acc[mt][nt][2], acc[mt][nt][3]);
        }
    }
}

// ======================= GEMM2: tf32 mma, x_dbl[T,56] = xc[T,768] @ W_xproj =======================
#define G2P_ 36

__global__ void __launch_bounds__(256, 2) k_gemm2(const float* __restrict__ A,
                                                  const float* __restrict__ Bt,
                                                  float* __restrict__ C) {
    __shared__ uint32_t sA[128 * G2P_];
    __shared__ uint32_t sB[64 * G2P_];
    int tid = threadIdx.x;
    int lane = tid & 31, wid = tid >> 5;
    int wm = wid >> 1, wn = wid & 1;
    int gid = lane >> 2, tig = lane & 3;
    int m0 = blockIdx.x * 128;

    float acc[2][4][4];
    #pragma unroll
    for (int i = 0; i < 2; i++)
        #pragma unroll
        for (int j = 0; j < 4; j++)
            #pragma unroll
            for (int q = 0; q < 4; q++) acc[i][j][q] = 0.f;

    for (int k0 = 0; k0 < DI_; k0 += 32) {
        #pragma unroll
        for (int i = 0; i < 4; i++) {
            int f = tid + i * 256;
            int row = f >> 3, c4 = f & 7;
            float4 v = *(const float4*)&A[(size_t)(m0 + row) * DI_ + k0 + c4 * 4];
            uint32_t* d = &sA[row * G2P_ + c4 * 4];
            d[0] = f2tf32(v.x); d[1] = f2tf32(v.y); d[2] = f2tf32(v.z); d[3] = f2tf32(v.w);
        }
        #pragma unroll
        for (int i = 0; i < 2; i++) {
            int f = tid + i * 256;
            int row = f >> 3, c4 = f & 7;
            float4 v = *(const float4*)&Bt[(size_t)row * DI_ + k0 + c4 * 4];
            uint32_t* d = &sB[row * G2P_ + c4 * 4];
            d[0] = f2tf32(v.x); d[1] = f2tf32(v.y); d[2] = f2tf32(v.z); d[3] = f2tf32(v.w);
        }
        __syncthreads();
        #pragma unroll
        for (int kk = 0; kk < 32; kk += 8) {
            uint32_t af[2][4], bf[4][2];
            #pragma unroll
            for (int mt = 0; mt < 2; mt++) {
                int r = wm * 32 + mt * 16 + gid;
                af[mt][0] = sA[r * G2P_ + kk + tig];
                af[mt][1] = sA[(r + 8) * G2P_ + kk + tig];
                af[mt][2] = sA[r * G2P_ + kk + tig + 4];
                af[mt][3] = sA[(r + 8) * G2P_ + kk + tig + 4];
            }
            #pragma unroll
            for (int nt = 0; nt < 4; nt++) {
                int r = wn * 32 + nt * 8 + gid;
                bf[nt][0] = sB[r * G2P_ + kk + tig];
                bf[nt][1] = sB[r * G2P_ + kk + tig + 4];
            }
            #pragma unroll
            for (int mt = 0; mt < 2; mt++)
                #pragma unroll
                for (int nt = 0; nt < 4; nt++)
                    mma_tf32(acc[mt][nt], af[mt], bf[nt]);
        }
        __syncthreads();
    }
    #pragma unroll
    for (int mt = 0; mt < 2; mt++) {
        int row = m0 + wm * 32 + mt * 16 + gid;
        #pragma unroll
        for (int nt = 0; nt < 4; nt++) {
            int col = wn * 32 + nt * 8 + 2 * tig;
            if (col < XDN_) {
                *(float2*)&C[(size_t)row * XDN_ + col]       = make_float2(acc[mt][nt][0], acc[mt][nt][1]);
                *(float2*)&C[(size_t)(row + 8) * XDN_ + col] = make_float2(acc[mt][nt][2], acc[mt][nt][3]);
            }
        }
    }
}

// ======================= causal depthwise conv (K=4) + SiLU  [R3 exact] =======================
__global__ void k_conv(const float* __restrict__ conv_w, const float* __restrict__ conv_b) {
    int idx = blockIdx.x * 256 + threadIdx.x;
    if (idx >= T_ * DI_) return;
    int di = idx % DI_;
    int t  = idx / DI_;
    int l  = t & (L_ - 1);
    float acc = conv_b[di];
    #pragma unroll
    for (int k = 0; k < KC_; k++) {
        int ll = l - (KC_ - 1) + k;
        if (ll >= 0)
            acc = fmaf(conv_w[di * KC_ + k], g_xz[(size_t)(t - (KC_ - 1) + k) * NI_ + di], acc);
    }
    float sg = 1.f / (1.f + __expf(-acc));
    float v = acc * sg;
    g_xc[(size_t)t * DI_ + di] = v;
    g_dtx[((size_t)t * DI_ + di) * 2 + 1] = v;
}

// ======================= dt = softplus(dt_r @ W_dt + bias)  [R3 exact] =======================
__global__ void k_dt(const float* __restrict__ W_dt, const float* __restrict__ dt_bias) {
    __shared__ float s_dtr[8][DTR_];
    int t0 = blockIdx.x * 8;
    int tid = threadIdx.x;
    if (tid < 8 * DTR_) {
        int tt = tid / DTR_, rr = tid % DTR_;
        s_dtr[tt][rr] = g_xdbl[(size_t)(t0 + tt) * XDN_ + rr];
    }
    __syncthreads();
    int di = tid;
    float bias = dt_bias[di];
    float acc[8];
    #pragma unroll
    for (int tt = 0; tt < 8; tt++) acc[tt] = bias;
    for (int rr = 0; rr < DTR_; rr++) {
        float w = W_dt[rr * DI_ + di];
        #pragma unroll
        for (int tt = 0; tt < 8; tt++) acc[tt] = fmaf(s_dtr[tt][rr], w, acc[tt]);
    }
    #pragma unroll
    for (int tt = 0; tt < 8; tt++) {
        float v = acc[tt];
        float sp = (v > 20.f) ? v : log1pf(__expf(v));
        g_dtx[((size_t)(t0 + tt) * DI_ + di) * 2 + 0] = sp;
    }
}

// ======================= pack (B,C) interleaved  [R3 exact] =======================
__global__ void k_bcpack() {
    int idx = blockIdx.x * 256 + threadIdx.x;
    if (idx >= T_ * S_) return;
    int t = idx >> 4, s = idx & 15;
    float bv = g_xdbl[(size_t)t * XDN_ + DTR_ + s];
    float cv = g_xdbl[(size_t)t * XDN_ + DTR_ + S_ + s];
    ((float2*)g_bc)[idx] = make_float2(bv, cv);
}

// ======================= selective scan  [R3 exact] =======================
__global__ void __launch_bounds__(128) k_scan2(const float* __restrict__ A_log) {
    int dg = blockIdx.x, b = blockIdx.y;
    int di_local = threadIdx.x >> 4;
    int s        = threadIdx.x & 15;
    int di = dg * 8 + di_local;
    float A = -__expf(A_log[di * S_ + s]);
    float h = 0.f;
    size_t tbase = (size_t)b * L_;
    const float2* dtx = (const float2*)g_dtx;
    const float2* bc  = (const float2*)g_bc;
    for (int l = 0; l < L_; l += 4) {
        float2 dx[4], bcv[4];
        #pragma unroll
        for (int j = 0; j < 4; j++) {
            size_t t = tbase + l + j;
            dx[j]  = dtx[t * DI_ + di];
            bcv[j] = bc[t * S_ + s];
        }
        #pragma unroll
        for (int j = 0; j < 4; j++) {
            float dtv = dx[j].x, xv = dx[j].y;
            float dA = __expf(dtv * A);
            h = fmaf(dA, h, dtv * xv * bcv[j].x);
            float yp = h * bcv[j].y;
            yp += __shfl_xor_sync(0xffffffffu, yp, 8);
            yp += __shfl_xor_sync(0xffffffffu, yp, 4);
            yp += __shfl_xor_sync(0xffffffffu, yp, 2);
            yp += __shfl_xor_sync(0xffffffffu, yp, 1);
            if (s == 0) g_y[(tbase + l + j) * DI_ + di] = yp;
        }
    }
}

// ======================= pooled-mean pipeline  [R3 exact] =======================
__global__ void k_ypart(const float* __restrict__ Dskip) {
    int di    = blockIdx.x * 256 + threadIdx.x;
    int chunk = blockIdx.y;
    int b     = blockIdx.z;
    float ds = Dskip[di];
    float acc = 0.f;
    int t0 = b * L_ + chunk * 64;
    for (int i = 0; i < 64; i++) {
        int t = t0 + i;
        float z  = g_xz[(size_t)t * NI_ + DI_ + di];
        float sz = z / (1.f + __expf(-z));
        acc += (g_y[(size_t)t * DI_ + di] + g_xc[(size_t)t * DI_ + di] * ds) * sz;
    }
    g_ypart[(size_t)(chunk * B_ + b) * DI_ + di] = acc;
}
__global__ void k_ymean() {
    int i = blockIdx.x * 256 + threadIdx.x;
    float acc = 0.f;
    for (int c = 0; c < 64; c++) acc += g_ypart[(size_t)c * B_ * DI_ + i];
    g_ym[i] = acc * (1.f / L_);
}
__global__ void k_xpart(const float* __restrict__ x) {
    int d = threadIdx.x;
    int chunk = blockIdx.x;
    int b = blockIdx.y;
    float acc = 0.f;
    int t0 = b * L_ + chunk * 64;
    for (int i = 0; i < 64; i++) acc += x[(size_t)(t0 + i) * D_ + d];
    g_xpart[(size_t)(chunk * B_ + b) * D_ + d] = acc;
}
__global__ void k_xmean() {
    int i = blockIdx.x * 256 + threadIdx.x;
    float acc = 0.f;
    for (int c = 0; c < 64; c++) acc += g_xpart[(size_t)c * B_ * D_ + i];
    g_xmean[i] = acc * (1.f / L_);
}
__global__ void k_pooled(const float* __restrict__ W_out) {
    int d = threadIdx.x;
    int b = blockIdx.x;
    float acc = g_xmean[b * D_ + d];
    for (int di = 0; di < DI_; di++)
        acc = fmaf(g_ym[b * DI_ + di], W_out[(size_t)di * D_ + d], acc);
    g_pooled[b * D_ + d] = acc;
}

// ======================= head  [R3 exact] =======================
__global__ void k_head(const float* __restrict__ W_fc, const float* __restrict__ b_fc,
                       const float* __restrict__ gamma, const float* __restrict__ beta,
                       const float* __restrict__ W_cls, const float* __restrict__ b_cls,
                       float* __restrict__ out) {
    __shared__ float sp[B_][D_];
    __shared__ float sh[B_][256];
    int tid = threadIdx.x;
    for (int i = tid; i < B_ * D_; i += 256) sp[i / D_][i % D_] = g_pooled[i];
    __syncthreads();
    int j = tid;
    float hv[B_];
    #pragma unroll
    for (int b = 0; b < B_; b++) hv[b] = b_fc[j];
    for (int k = 0; k < D_; k++) {
        float w = W_fc[(size_t)k * 256 + j];
        #pragma unroll
        for (int b = 0; b < B_; b++) hv[b] = fmaf(sp[b][k], w, hv[b]);
    }
    float mu = 0.f;
    #pragma unroll
    for (int b = 0; b < B_; b++) mu += hv[b];
    mu *= (1.f / B_);
    float var = 0.f;
    #pragma unroll
    for (int b = 0; b < B_; b++) { float dd = hv[b] - mu; var += dd * dd; }
    var *= (1.f / B_);
    float rs = rsqrtf(var + EPS_);
    float g = gamma[j], bt = beta[j];
    #pragma unroll
    for (int b = 0; b < B_; b++) {
        float v = (hv[b] - mu) * rs * g + bt;
        sh[b][j] = v > 0.f ? v : 0.f;
    }
    __syncthreads();
    for (int o = tid; o < B_ * NC_; o += 256) {
        int b = o / NC_, c = o % NC_;
        float acc = b_cls[c];
        for (int k = 0; k < 256; k++) acc = fmaf(sh[b][k], W_cls[k * NC_ + c], acc);
        out[o] = acc;
    }
}

// ======================= launch =======================
extern "C" void kernel_launch(void* const* d_in, const int* in_sizes, int n_in,
                              void* d_out, int out_size) {
    const float* x       = (const float*)d_in[0];
    const float* ln_w    = (const float*)d_in[1];
    const float* W_in    = (const float*)d_in[2];
    const float* conv_w  = (const float*)d_in[3];
    const float* conv_b  = (const float*)d_in[4];
    const float* W_xproj = (const float*)d_in[5];
    const float* W_dt    = (const float*)d_in[6];
    const float* dt_bias = (const float*)d_in[7];
    const float* A_log   = (const float*)d_in[8];
    const float* Dskip   = (const float*)d_in[9];
    const float* W_out   = (const float*)d_in[10];
    const float* W_fc    = (const float*)d_in[11];
    const float* b_fc    = (const float*)d_in[12];
    const float* bn_g    = (const float*)d_in[13];
    const float* bn_b    = (const float*)d_in[14];
    const float* W_cls   = (const float*)d_in[15];
    const float* b_cls   = (const float*)d_in[16];
    float* out = (float*)d_out;

    __half *p_xnh, *p_wth;
    float *p_xz, *p_xc, *p_wt2, *p_xdbl;
    cudaGetSymbolAddress((void**)&p_xnh,  g_xnh);
    cudaGetSymbolAddress((void**)&p_wth,  g_wth);
    cudaGetSymbolAddress((void**)&p_xz,   g_xz);
    cudaGetSymbolAddress((void**)&p_xc,   g_xc);
    cudaGetSymbolAddress((void**)&p_wt2,  g_wt2);
    cudaGetSymbolAddress((void**)&p_xdbl, g_xdbl);

    // 1. RMSNorm (half out) + weight transposes
    k_rmsnorm<<<T_, 128>>>(x, ln_w);
    k_wt<<<dim3(D_ / 32, NI_ / 32), 256>>>(W_in);
    k_wt2<<<dim3(DI_ / 32, 2), 256>>>(W_xproj);
    // 2. xz = xn @ W_in — fp16 mma (4th launch -> profiled)
    k_gemm1<<<dim3(NI_ / 128, T_ / 128), 256>>>(p_xnh, p_wth, p_xz);
    // 3. conv + silu (writes xc and dtx.y)
    k_conv<<<(T_ * DI_ + 255) / 256, 256>>>(conv_w, conv_b);
    // 4. x_dbl = xc @ W_xproj — tf32 mma
    k_gemm2<<<T_ / 128, 256>>>(p_xc, p_wt2, p_xdbl);
    // 5. dt (writes dtx.x) and BC pack
    k_dt<<<T_ / 8, DI_>>>(W_dt, dt_bias);
    k_bcpack<<<(T_ * S_ + 255) / 256, 256>>>();
    // 6. selective scan (R3 single pass)
    k_scan2<<<dim3(DI_ / 8, B_), 128>>>(A_log);
    // 7. means + pooled + head
    k_ypart<<<dim3(DI_ / 256, 64, B_), 256>>>(Dskip);
    k_ymean<<<(B_ * DI_) / 256, 256>>>();
    k_xpart<<<dim3(64, B_), D_>>>(x);
    k_xmean<<<(B_ * D_) / 256, 256>>>();
    k_pooled<<<B_, D_>>>(W_out);
    k_head<<<1, 256>>>(W_fc, b_fc, bn_g, bn_b, W_cls, b_cls, out);
}